// round 3
// baseline (speedup 1.0000x reference)
#include <cuda_runtime.h>
#include <math_constants.h>

// DeepSeek-V3 grouped top-k router.
// T=131072 tokens, E=256 experts, G=8 groups x 32, top-2-sum group score,
// top-4 groups, top-8 experts, weights = unbiased logits renormalized * 2.5.
//
// One warp per token. Lane l owns experts [l*8, l*8+8).
// Output layout assumption: d_out = [weights (T*8 f32) | ids (T*8 as f32)].

#define NEXP        256
#define GROUPS      8
#define TOPK        8
#define TOPK_GROUP  4
#define SCALE       2.5f
#define NEG_INF     (-CUDART_INF_F)

__global__ __launch_bounds__(256, 4)
void topk_router_kernel(const float* __restrict__ logits,
                        const float* __restrict__ bias,
                        float* __restrict__ out_w,
                        float* __restrict__ out_id,
                        int T)
{
    const int warp_id = (blockIdx.x * blockDim.x + threadIdx.x) >> 5;
    const int lane    = threadIdx.x & 31;
    if (warp_id >= T) return;

    const float* row = logits + (size_t)warp_id * NEXP;

    // ---- load 8 logits + 8 biases per lane (coalesced 128-bit) ----
    float l[8];   // raw logits (kept exact for weight gather)
    float s[8];   // biased scores
    {
        float4 a = *reinterpret_cast<const float4*>(row + lane * 8);
        float4 b = *reinterpret_cast<const float4*>(row + lane * 8 + 4);
        l[0]=a.x; l[1]=a.y; l[2]=a.z; l[3]=a.w;
        l[4]=b.x; l[5]=b.y; l[6]=b.z; l[7]=b.w;
        float4 ba = *reinterpret_cast<const float4*>(bias + lane * 8);
        float4 bb = *reinterpret_cast<const float4*>(bias + lane * 8 + 4);
        s[0]=l[0]+ba.x; s[1]=l[1]+ba.y; s[2]=l[2]+ba.z; s[3]=l[3]+ba.w;
        s[4]=l[4]+bb.x; s[5]=l[5]+bb.y; s[6]=l[6]+bb.z; s[7]=l[7]+bb.w;
    }

    // ---- lane-local top-2 of its 8 biased scores ----
    float m1 = NEG_INF, m2 = NEG_INF;
    #pragma unroll
    for (int j = 0; j < 8; j++) {
        float v = s[j];
        if (v > m1) { m2 = m1; m1 = v; }
        else        { m2 = fmaxf(m2, v); }
    }
    // ---- merge top-2 across the 4 lanes of each group (lanes 4g..4g+3) ----
    #pragma unroll
    for (int off = 1; off < 4; off <<= 1) {
        float o1 = __shfl_xor_sync(0xFFFFFFFFu, m1, off);
        float o2 = __shfl_xor_sync(0xFFFFFFFFu, m2, off);
        float n1 = fmaxf(m1, o1);
        float n2 = fmaxf(fminf(m1, o1), (m1 >= o1) ? m2 : o2);
        m1 = n1; m2 = n2;
    }
    const float gs = m1 + m2;          // group score, replicated within group
    const int   g  = lane >> 2;        // my group id

    // ---- pick top-4 groups: rank my group among all 8 ----
    int rank = 0;
    #pragma unroll
    for (int h = 0; h < GROUPS; h++) {
        float gh = __shfl_sync(0xFFFFFFFFu, gs, h << 2);
        rank += (gh > gs) || (gh == gs && h < g);
    }
    if (rank >= TOPK_GROUP) {
        #pragma unroll
        for (int j = 0; j < 8; j++) s[j] = NEG_INF;
    }

    // ---- lane-local argmax of remaining scores ----
    float lv = s[0]; int li = 0;
    #pragma unroll
    for (int j = 1; j < 8; j++) {
        if (s[j] > lv) { lv = s[j]; li = j; }
    }

    // ---- iterative top-8 extraction across the warp ----
    float wsum = 0.0f;
    float myw  = 0.0f;
    int   myid = 0;
    #pragma unroll
    for (int it = 0; it < TOPK; it++) {
        // warp max (value only; ties resolved by lowest lane below, which is
        // lowest expert index — matches jax.lax.top_k tie-break)
        float mv = lv;
        #pragma unroll
        for (int off = 16; off > 0; off >>= 1)
            mv = fmaxf(mv, __shfl_xor_sync(0xFFFFFFFFu, mv, off));

        unsigned bal = __ballot_sync(0xFFFFFFFFu, lv == mv);
        int wlane = __ffs(bal) - 1;
        int wslot = __shfl_sync(0xFFFFFFFFu, li, wlane);
        int idx   = (wlane << 3) + wslot;

        // exact unbiased logit from winner lane (predicated select chain)
        float cand = l[0];
        #pragma unroll
        for (int j = 1; j < 8; j++)
            if (wslot == j) cand = l[j];
        float w = __shfl_sync(0xFFFFFFFFu, cand, wlane);

        wsum += w;
        if (lane == it) { myw = w; myid = idx; }

        // winner lane removes its entry and recomputes local max
        if (lane == wlane) {
            s[wslot] = NEG_INF;
            lv = s[0]; li = 0;
            #pragma unroll
            for (int j = 1; j < 8; j++) {
                if (s[j] > lv) { lv = s[j]; li = j; }
            }
        }
    }

    // ---- normalize + scale, write out ----
    const float inv = SCALE / wsum;
    if (lane < TOPK) {
        out_w [(size_t)warp_id * TOPK + lane] = myw * inv;
        out_id[(size_t)warp_id * TOPK + lane] = (float)myid;
    }
}

extern "C" void kernel_launch(void* const* d_in, const int* in_sizes, int n_in,
                              void* d_out, int out_size)
{
    const float* logits = (const float*)d_in[0];
    const float* bias   = (const float*)d_in[1];
    const int T = in_sizes[0] / NEXP;

    float* out_w  = (float*)d_out;
    float* out_id = out_w + (size_t)T * TOPK;   // second half of d_out

    const int threads = 256;                    // 8 warps = 8 tokens/block
    const int blocks  = (T + (threads / 32) - 1) / (threads / 32);
    topk_router_kernel<<<blocks, threads>>>(logits, bias, out_w, out_id, T);
}

// round 4
// speedup vs baseline: 1.5136x; 1.5136x over previous
#include <cuda_runtime.h>

// DeepSeek-V3 grouped top-k router, round 3.
// T tokens x 256 experts, 8 groups x 32, group score = sum of top-2 biased
// scores, top-4 groups, top-8 experts, weights = unbiased logits renorm * 2.5.
//
// One warp per token; lane l owns experts [8l, 8l+8) (all in group l>>2).
// Strategy: per-lane Batcher-sort of 8 packed keys (exact score+slot order),
// then 8 rounds of REDUX.MAX warp-argmax with shrinking-window shift-pop.
// Raw logits for weights are re-gathered from L1 at the end (exact values).

#define FULL 0xFFFFFFFFu
#define TOPK 8
#define SCALE 2.5f

__device__ __forceinline__ unsigned f2ord(float f) {
    unsigned u = __float_as_uint(f);
    // monotonic float->uint map: compare as unsigned == compare as float
    return u ^ (unsigned)(((int)u >> 31) | 0x80000000);
}
__device__ __forceinline__ float ord2f(unsigned v) {
    return __uint_as_float((v & 0x80000000u) ? (v ^ 0x80000000u) : ~v);
}

// descending compare-exchange: max to lower index
#define CE(i, j)                                              \
    {                                                         \
        unsigned long long _a = k[i], _b = k[j];              \
        bool _p = _a < _b;                                    \
        k[i] = _p ? _b : _a;                                  \
        k[j] = _p ? _a : _b;                                  \
    }

__global__ __launch_bounds__(256)
void topk_router_kernel(const float* __restrict__ logits,
                        const float* __restrict__ bias,
                        float* __restrict__ out_w,
                        float* __restrict__ out_id,
                        int T)
{
    const int warp = (blockIdx.x * blockDim.x + threadIdx.x) >> 5;
    const int lane = threadIdx.x & 31;
    if (warp >= T) return;

    const float* row = logits + (size_t)warp * 256;

    // ---- coalesced 128-bit loads: 8 logits + 8 biases per lane ----
    float4 a  = __ldg(reinterpret_cast<const float4*>(row + lane * 8));
    float4 b  = __ldg(reinterpret_cast<const float4*>(row + lane * 8 + 4));
    float4 ba = __ldg(reinterpret_cast<const float4*>(bias + lane * 8));
    float4 bb = __ldg(reinterpret_cast<const float4*>(bias + lane * 8 + 4));

    // packed keys: (ordered biased score << 32) | (7 - slot)
    // -> u64 descending order == (score desc, slot asc): exact JAX tie-break
    unsigned long long k[8];
    k[0] = ((unsigned long long)f2ord(a.x + ba.x) << 32) | 7u;
    k[1] = ((unsigned long long)f2ord(a.y + ba.y) << 32) | 6u;
    k[2] = ((unsigned long long)f2ord(a.z + ba.z) << 32) | 5u;
    k[3] = ((unsigned long long)f2ord(a.w + ba.w) << 32) | 4u;
    k[4] = ((unsigned long long)f2ord(b.x + bb.x) << 32) | 3u;
    k[5] = ((unsigned long long)f2ord(b.y + bb.y) << 32) | 2u;
    k[6] = ((unsigned long long)f2ord(b.z + bb.z) << 32) | 1u;
    k[7] = ((unsigned long long)f2ord(b.w + bb.w) << 32) | 0u;

    // ---- Batcher odd-even mergesort, 19 CEs, descending ----
    CE(0,1) CE(2,3) CE(4,5) CE(6,7)
    CE(0,2) CE(1,3) CE(4,6) CE(5,7)
    CE(1,2) CE(5,6)
    CE(0,4) CE(1,5) CE(2,6) CE(3,7)
    CE(2,4) CE(3,5)
    CE(1,2) CE(3,4) CE(5,6)

    // ---- group score = top-2 sum; per-lane top-2 comes free from the sort ----
    float m1 = ord2f((unsigned)(k[0] >> 32));
    float m2 = ord2f((unsigned)(k[1] >> 32));
    #pragma unroll
    for (int off = 1; off < 4; off <<= 1) {          // merge 4 lanes of group
        float o1 = __shfl_xor_sync(FULL, m1, off);
        float o2 = __shfl_xor_sync(FULL, m2, off);
        float n2 = fmaxf(fminf(m1, o1), (m1 >= o1) ? m2 : o2);
        m1 = fmaxf(m1, o1);
        m2 = n2;
    }
    const float gs = m1 + m2;                        // replicated within group
    const int   g  = lane >> 2;

    // rank my group among 8 (ties -> lower group index wins, as in top_k)
    int rank = 0;
    #pragma unroll
    for (int h = 0; h < 8; h++) {
        float gh = __shfl_sync(FULL, gs, h << 2);
        rank += (gh > gs) || (gh == gs && h < g);
    }
    const bool alive = rank < 4;

    // ---- 8 extraction rounds: REDUX argmax + shrinking shift-pop ----
    unsigned myid = 0;
    #pragma unroll
    for (int it = 0; it < TOPK; it++) {
        unsigned hk  = alive ? (unsigned)(k[0] >> 32) : 0u;   // dead lanes -> 0
        unsigned m   = __reduce_max_sync(FULL, hk);
        unsigned bal = __ballot_sync(FULL, hk == m);
        int wl       = __ffs(bal) - 1;                // lowest lane = lowest idx
        unsigned lo  = __shfl_sync(FULL, (unsigned)k[0], wl); // winner's 7-slot
        unsigned id  = ((unsigned)wl << 3) + (7u - (lo & 7u));
        if (lane == it) myid = id;

        // winner pops its head; depth > 6-it can never be read again
        bool amw = (lane == wl);
        #pragma unroll
        for (int d = 0; d < 7 - it; d++)
            if (amw) k[d] = k[d + 1];
    }

    // ---- weights: exact unbiased logits via L1-hit gather ----
    float w = 0.0f;
    if (lane < TOPK) w = __ldg(row + myid);
    float wsum = w;
    #pragma unroll
    for (int off = 1; off < 8; off <<= 1)             // sum over lanes 0..7
        wsum += __shfl_xor_sync(FULL, wsum, off);

    if (lane < TOPK) {
        size_t o = (size_t)warp * TOPK + lane;
        out_w[o]  = w * __fdividef(SCALE, wsum);
        out_id[o] = (float)myid;
    }
}

extern "C" void kernel_launch(void* const* d_in, const int* in_sizes, int n_in,
                              void* d_out, int out_size)
{
    const float* logits = (const float*)d_in[0];
    const float* bias   = (const float*)d_in[1];
    const int T = in_sizes[0] / 256;

    float* out_w  = (float*)d_out;
    float* out_id = out_w + (size_t)T * TOPK;   // [weights | ids] halves

    const int threads = 256;                    // 8 warps = 8 tokens / block
    const int blocks  = (T + 7) / 8;
    topk_router_kernel<<<blocks, threads>>>(logits, bias, out_w, out_id, T);
}

// round 5
// speedup vs baseline: 1.5990x; 1.0564x over previous
#include <cuda_runtime.h>

// DeepSeek-V3 grouped top-k router, round 4.
// 2 tokens per warp with register prefetch; exact u64 sort keys; REDUX argmax
// extraction with PRMT id packing. All tie-breaks bit-exact vs jax.lax.top_k.

#define FULL  0xFFFFFFFFu
#define TOPK  8
#define SCALE 2.5f

__device__ __forceinline__ unsigned f2ord(float f) {
    unsigned u = __float_as_uint(f);
    return u ^ (unsigned)(((int)u >> 31) | 0x80000000);   // monotonic f32->u32
}
__device__ __forceinline__ float ord2f(unsigned v) {
    return __uint_as_float((v & 0x80000000u) ? (v ^ 0x80000000u) : ~v);
}

// descending compare-exchange on u64 keys (max to lower index)
#define CE(i, j)                                              \
    {                                                         \
        unsigned long long _a = k[i], _b = k[j];              \
        bool _p = _a < _b;                                    \
        k[i] = _p ? _b : _a;                                  \
        k[j] = _p ? _a : _b;                                  \
    }

// byte_perm selectors: write id's low byte into byte `it` of accumulator
__device__ __forceinline__ unsigned prmt_sel(int it) {
    const unsigned s[4] = {0x3214u, 0x3240u, 0x3410u, 0x4210u};
    return s[it];
}

__global__ __launch_bounds__(128, 10)
void topk_router_kernel(const float* __restrict__ logits,
                        const float* __restrict__ bias,
                        float* __restrict__ out_w,
                        float* __restrict__ out_id,
                        int T)
{
    const int gwarp = (blockIdx.x * blockDim.x + threadIdx.x) >> 5;
    const int lane  = threadIdx.x & 31;
    const int g     = lane >> 2;

    int token = gwarp * 2;
    if (token >= T) return;

    // bias per lane (L1-hot after first warps)
    const float4 ba = __ldg(reinterpret_cast<const float4*>(bias + lane * 8));
    const float4 bb = __ldg(reinterpret_cast<const float4*>(bias + lane * 8 + 4));

    // first token's row
    const float* row = logits + (size_t)token * 256;
    float4 a = __ldg(reinterpret_cast<const float4*>(row + lane * 8));
    float4 b = __ldg(reinterpret_cast<const float4*>(row + lane * 8 + 4));

    #pragma unroll
    for (int t = 0; t < 2; t++) {
        // ---- pack exact keys: (ordered biased score << 32) | (7 - slot) ----
        unsigned long long k[8];
        k[0] = ((unsigned long long)f2ord(a.x + ba.x) << 32) | 7u;
        k[1] = ((unsigned long long)f2ord(a.y + ba.y) << 32) | 6u;
        k[2] = ((unsigned long long)f2ord(a.z + ba.z) << 32) | 5u;
        k[3] = ((unsigned long long)f2ord(a.w + ba.w) << 32) | 4u;
        k[4] = ((unsigned long long)f2ord(b.x + bb.x) << 32) | 3u;
        k[5] = ((unsigned long long)f2ord(b.y + bb.y) << 32) | 2u;
        k[6] = ((unsigned long long)f2ord(b.z + bb.z) << 32) | 1u;
        k[7] = ((unsigned long long)f2ord(b.w + bb.w) << 32) | 0u;

        // ---- prefetch next token's row: LDGs fly during sort+extraction ----
        if (t == 0 && token + 1 < T) {
            const float* nrow = row + 256;
            a = __ldg(reinterpret_cast<const float4*>(nrow + lane * 8));
            b = __ldg(reinterpret_cast<const float4*>(nrow + lane * 8 + 4));
        }

        // ---- Batcher odd-even mergesort of 8, descending, 19 CEs ----
        CE(0,1) CE(2,3) CE(4,5) CE(6,7)
        CE(0,2) CE(1,3) CE(4,6) CE(5,7)
        CE(1,2) CE(5,6)
        CE(0,4) CE(1,5) CE(2,6) CE(3,7)
        CE(2,4) CE(3,5)
        CE(1,2) CE(3,4) CE(5,6)

        // ---- group score = top-2 sum (head pair free from the sort) ----
        float m1 = ord2f((unsigned)(k[0] >> 32));
        float m2 = ord2f((unsigned)(k[1] >> 32));
        #pragma unroll
        for (int off = 1; off < 4; off <<= 1) {
            float o1 = __shfl_xor_sync(FULL, m1, off);
            float o2 = __shfl_xor_sync(FULL, m2, off);
            float n2 = fmaxf(fminf(m1, o1), (m1 >= o1) ? m2 : o2);
            m1 = fmaxf(m1, o1);
            m2 = n2;
        }
        const float gs = m1 + m2;

        // rank my group among 8 (ties -> lower group index, as in top_k)
        int rank = 0;
        #pragma unroll
        for (int h = 0; h < 8; h++) {
            float gh = __shfl_sync(FULL, gs, h << 2);
            rank += (gh > gs) || (gh == gs && h < g);
        }
        // dead lanes: zero only the head's hi word once. A dead lane can
        // never win (finite scores have ord > 0), so it never shifts.
        if (rank >= 4) k[0] &= 0xFFFFFFFFull;

        // ---- 8 extraction rounds: REDUX argmax + shrinking shift-pop ----
        unsigned p0 = 0, p1 = 0;     // packed ids, 1 byte per round
        #pragma unroll
        for (int it = 0; it < TOPK; it++) {
            unsigned hk  = (unsigned)(k[0] >> 32);
            unsigned m   = __reduce_max_sync(FULL, hk);
            unsigned bal = __ballot_sync(FULL, hk == m);
            int wl       = __ffs(bal) - 1;               // lowest lane wins tie
            unsigned lo  = __shfl_sync(FULL, (unsigned)k[0], wl);
            unsigned id  = ((unsigned)wl << 3) + (7u - (lo & 7u));

            if (it < 4) p0 = __byte_perm(p0, id, prmt_sel(it));
            else        p1 = __byte_perm(p1, id, prmt_sel(it - 4));

            bool amw = (lane == wl);
            #pragma unroll
            for (int d = 0; d < 7 - it; d++)
                if (amw) k[d] = k[d + 1];
        }

        // ---- weights: exact unbiased logits, L1-hot gather ----
        unsigned pk   = (lane < 4) ? p0 : p1;
        unsigned myid = (pk >> ((lane & 3) * 8)) & 255u;
        float w = 0.0f;
        if (lane < TOPK) w = __ldg(row + myid);
        float wsum = w;
        #pragma unroll
        for (int off = 1; off < 8; off <<= 1)
            wsum += __shfl_xor_sync(FULL, wsum, off);

        if (lane < TOPK) {
            size_t o = (size_t)token * TOPK + lane;
            out_w[o]  = w * __fdividef(SCALE, wsum);
            out_id[o] = (float)myid;
        }

        // advance to second token
        token += 1;
        if (token >= T) return;
        row += 256;
    }
}

extern "C" void kernel_launch(void* const* d_in, const int* in_sizes, int n_in,
                              void* d_out, int out_size)
{
    const float* logits = (const float*)d_in[0];
    const float* bias   = (const float*)d_in[1];
    const int T = in_sizes[0] / 256;

    float* out_w  = (float*)d_out;
    float* out_id = out_w + (size_t)T * TOPK;   // [weights | ids] halves

    const int threads = 128;                    // 4 warps, 2 tokens each
    const int tokens_per_block = (threads / 32) * 2;
    const int blocks = (T + tokens_per_block - 1) / tokens_per_block;
    topk_router_kernel<<<blocks, threads>>>(logits, bias, out_w, out_id, T);
}